// round 5
// baseline (speedup 1.0000x reference)
#include <cuda_runtime.h>
#include <cstdint>

#define TT 2048
#define BB 128
#define HH 256
#define II 64
#define NCTA 64
#define NTH 256
#define K0 (II + HH)
#define K1 (HH + HH)
#define LDW0 (K0 + 4)
#define LDW1 (K1 + 4)
#define SMEMB ((64 * LDW1 + 48) * 4)

__device__ float2 g_x2[TT * BB * II];     // x pre-split (hi, lo)
__device__ float2 g_h0[2][BB * HH];       // layer0 h, double buffered, (hi, lo)
__device__ float2 g_h1[2][BB * HH];       // layer1 h
__device__ unsigned g_cnt;
__device__ unsigned g_gen;

__device__ __forceinline__ void gbar() {
    __syncthreads();
    if (threadIdx.x == 0) {
        unsigned old = *((volatile unsigned*)&g_gen);
        __threadfence();
        if (atomicAdd(&g_cnt, 1u) == NCTA - 1) {
            atomicExch(&g_cnt, 0u);
            __threadfence();
            atomicAdd(&g_gen, 1u);
        } else {
            while (*((volatile unsigned*)&g_gen) == old) { }
        }
        __threadfence();
    }
    __syncthreads();
}

__device__ __forceinline__ void split(float x, unsigned& hi, unsigned& lo) {
    asm("cvt.rna.tf32.f32 %0, %1;" : "=r"(hi) : "f"(x));
    float r = x - __uint_as_float(hi);
    asm("cvt.rna.tf32.f32 %0, %1;" : "=r"(lo) : "f"(r));
}

__device__ __forceinline__ float2 split2(float x) {
    unsigned hi, lo;
    split(x, hi, lo);
    return make_float2(__uint_as_float(hi), __uint_as_float(lo));
}

__device__ __forceinline__ void mma8(float (&c)[4], float a0, float a1,
                                     float a2, float a3, float b0, float b1) {
    asm volatile(
        "mma.sync.aligned.m16n8k8.row.col.f32.tf32.tf32.f32 "
        "{%0,%1,%2,%3},{%4,%5,%6,%7},{%8,%9},{%0,%1,%2,%3};"
        : "+f"(c[0]), "+f"(c[1]), "+f"(c[2]), "+f"(c[3])
        : "r"(__float_as_uint(a0)), "r"(__float_as_uint(a1)),
          "r"(__float_as_uint(a2)), "r"(__float_as_uint(a3)),
          "r"(__float_as_uint(b0)), "r"(__float_as_uint(b1)));
}

__device__ __forceinline__ float sigm(float x) { return 1.0f / (1.0f + __expf(-x)); }
__device__ __forceinline__ float tanhx(float x) { return 1.0f - 2.0f / (__expf(2.0f * x) + 1.0f); }

// A: row-major [BB, lda] of pre-split (hi,lo) pairs, L2-coherent loads.
// Weights hi/lo in SMEM, pair-interleaved so (b[k+kk], b[k+kk+4]) = one float2.
__device__ __forceinline__ void gemm_span(float (&acc)[4][4],
                                          const float2* __restrict__ A, int lda,
                                          int kbeg, int kend,
                                          const float* __restrict__ WHi,
                                          const float* __restrict__ WLo,
                                          int ldw, int r0, int lane) {
    const int kk = lane & 3;
    const int gq = lane >> 2;
    const float2* pa = A + r0 * lda + kk - kbeg;
    const float2* pb = pa + 8 * lda;
#pragma unroll 4
    for (int k = kbeg; k < kend; k += 8) {
        float2 e0 = __ldcg(pa + k);
        float2 e1 = __ldcg(pb + k);
        float2 e2 = __ldcg(pa + k + 4);
        float2 e3 = __ldcg(pb + k + 4);
#pragma unroll
        for (int g = 0; g < 4; ++g) {
            int off = (g * 8 + gq) * ldw + k + 2 * kk;
            float2 bh = *reinterpret_cast<const float2*>(WHi + off);
            float2 bl = *reinterpret_cast<const float2*>(WLo + off);
            mma8(acc[g], e0.x, e1.x, e2.x, e3.x, bh.x, bh.y);
            mma8(acc[g], e0.y, e1.y, e2.y, e3.y, bh.x, bh.y);
            mma8(acc[g], e0.x, e1.x, e2.x, e3.x, bl.x, bl.y);
        }
    }
}

__global__ void __launch_bounds__(NTH, 1)
lstm_kernel(const float* __restrict__ x, const float* __restrict__ h0in,
            const float* __restrict__ c0in,
            const float* __restrict__ Wih0, const float* __restrict__ Whh0,
            const float* __restrict__ bih0, const float* __restrict__ bhh0,
            const float* __restrict__ Wih1, const float* __restrict__ Whh1,
            const float* __restrict__ bih1, const float* __restrict__ bhh1,
            const float* __restrict__ Wlin, const float* __restrict__ blin,
            float* __restrict__ out) {
    extern __shared__ float sh[];
    const int tid = threadIdx.x;
    const int cta = blockIdx.x;
    const int layer = cta >> 5;        // 32 CTAs per layer
    const int sub = cta & 31;
    const int cb = sub * 8;            // first hidden column (8 per CTA)
    const int K = layer ? K1 : K0;
    const int ldw = layer ? LDW1 : LDW0;
    const int KX = layer ? HH : II;
    const float* Wih = layer ? Wih1 : Wih0;
    const float* Whh = layer ? Whh1 : Whh0;
    const float* bi = layer ? bih1 : bih0;
    const float* bh = layer ? bhh1 : bhh0;

    float* WHi = sh;
    float* WLo = sh + 32 * ldw;
    float* bs = sh + 64 * ldw;
    float* wl = bs + 32;

    // init: pre-split x, h0 buffers, out = b_lin
    {
        int g = cta * NTH + tid, gs = NCTA * NTH;
        for (int i = g; i < TT * BB * II; i += gs) g_x2[i] = split2(x[i]);
        for (int i = g; i < BB * HH; i += gs) {
            g_h0[1][i] = split2(h0in[i]);
            g_h1[1][i] = split2(h0in[BB * HH + i]);
        }
        float bl = blin[0];
        for (int i = g; i < TT * BB; i += gs) out[i] = bl;
    }

    // stage split weights (pair-interleaved within each 8-col k-group)
    for (int i = tid; i < 32 * K; i += NTH) {
        int n = i / K, k = i - n * K;
        int row = (n >> 3) * HH + cb + (n & 7);
        float wv = (k < KX) ? Wih[row * KX + k] : Whh[row * HH + (k - KX)];
        unsigned hi, lo;
        split(wv, hi, lo);
        int ko = n * ldw + (k & ~7) + 2 * (k & 3) + ((k >> 2) & 1);
        WHi[ko] = __uint_as_float(hi);
        WLo[ko] = __uint_as_float(lo);
    }
    if (tid < 32) {
        int row = (tid >> 3) * HH + cb + (tid & 7);
        bs[tid] = bi[row] + bh[row];
    }
    if (tid < 8) wl[tid] = layer ? Wlin[cb + tid] : 0.0f;
    __syncthreads();

    const int w = tid >> 5;            // 8 warps
    const int lane = tid & 31;
    const int r0 = 16 * w + (lane >> 2);   // batch rows r0, r0+8 (0..127)
    const int j0 = 2 * (lane & 3);
    const float* c0p = c0in + layer * BB * HH;
    float cs[4];
    cs[0] = c0p[r0 * HH + cb + j0];
    cs[1] = c0p[r0 * HH + cb + j0 + 1];
    cs[2] = c0p[(r0 + 8) * HH + cb + j0];
    cs[3] = c0p[(r0 + 8) * HH + cb + j0 + 1];

    float bz0[4], bz1[4];
#pragma unroll
    for (int g = 0; g < 4; ++g) {
        bz0[g] = bs[g * 8 + j0];
        bz1[g] = bs[g * 8 + j0 + 1];
    }
    const float wl0 = wl[j0], wl1 = wl[j0 + 1];

    gbar();

#pragma unroll 1
    for (int s = 0; s <= TT; ++s) {
        if (layer == 0) {
            if (s < TT) {
                float acc[4][4];
#pragma unroll
                for (int g = 0; g < 4; ++g) {
                    acc[g][0] = bz0[g]; acc[g][1] = bz1[g];
                    acc[g][2] = bz0[g]; acc[g][3] = bz1[g];
                }
                gemm_span(acc, g_x2 + (size_t)s * (BB * II), II, 0, II, WHi, WLo, ldw, r0, lane);
                gemm_span(acc, g_h0[(s + 1) & 1], HH, II, K0, WHi, WLo, ldw, r0, lane);
                float2* hb2 = g_h0[s & 1];
#pragma unroll
                for (int e = 0; e < 4; ++e) {
                    float ig = sigm(acc[0][e]);
                    float fg = sigm(acc[1][e]);
                    float gg = tanhx(acc[2][e]);
                    float og = sigm(acc[3][e]);
                    float c = fg * cs[e] + ig * gg;
                    cs[e] = c;
                    float hv = og * tanhx(c);
                    int rr = (e & 2) ? (r0 + 8) : r0;
                    hb2[rr * HH + cb + j0 + (e & 1)] = split2(hv);
                }
            }
        } else {
            if (s >= 1) {
                int t = s - 1;
                float acc[4][4];
#pragma unroll
                for (int g = 0; g < 4; ++g) {
                    acc[g][0] = bz0[g]; acc[g][1] = bz1[g];
                    acc[g][2] = bz0[g]; acc[g][3] = bz1[g];
                }
                gemm_span(acc, g_h0[t & 1], HH, 0, HH, WHi, WLo, ldw, r0, lane);
                gemm_span(acc, g_h1[s & 1], HH, HH, K1, WHi, WLo, ldw, r0, lane);
                float2* hb2 = g_h1[t & 1];
                float h[4];
#pragma unroll
                for (int e = 0; e < 4; ++e) {
                    float ig = sigm(acc[0][e]);
                    float fg = sigm(acc[1][e]);
                    float gg = tanhx(acc[2][e]);
                    float og = sigm(acc[3][e]);
                    float c = fg * cs[e] + ig * gg;
                    cs[e] = c;
                    h[e] = og * tanhx(c);
                    int rr = (e & 2) ? (r0 + 8) : r0;
                    hb2[rr * HH + cb + j0 + (e & 1)] = split2(h[e]);
                }
                float p0 = h[0] * wl0 + h[1] * wl1;
                float p1 = h[2] * wl0 + h[3] * wl1;
                p0 += __shfl_xor_sync(0xffffffffu, p0, 1);
                p0 += __shfl_xor_sync(0xffffffffu, p0, 2);
                p1 += __shfl_xor_sync(0xffffffffu, p1, 1);
                p1 += __shfl_xor_sync(0xffffffffu, p1, 2);
                if ((lane & 3) == 0) {
                    atomicAdd(out + (size_t)t * BB + r0, p0);
                    atomicAdd(out + (size_t)t * BB + r0 + 8, p1);
                }
            }
        }
        gbar();
    }
}

extern "C" void kernel_launch(void* const* d_in, const int* in_sizes, int n_in,
                              void* d_out, int out_size) {
    (void)in_sizes; (void)n_in; (void)out_size;
    cudaFuncSetAttribute(lstm_kernel, cudaFuncAttributeMaxDynamicSharedMemorySize, SMEMB);
    lstm_kernel<<<NCTA, NTH, SMEMB>>>(
        (const float*)d_in[0], (const float*)d_in[1], (const float*)d_in[2],
        (const float*)d_in[3], (const float*)d_in[4], (const float*)d_in[5],
        (const float*)d_in[6], (const float*)d_in[7], (const float*)d_in[8],
        (const float*)d_in[9], (const float*)d_in[10], (const float*)d_in[11],
        (const float*)d_in[12], (float*)d_out);
}

// round 6
// speedup vs baseline: 1.2884x; 1.2884x over previous
#include <cuda_runtime.h>
#include <cstdint>

#define TT 2048
#define BB 128
#define HH 256
#define II 64
#define NCTA 128
#define NTH 128
#define K0 (II + HH)
#define K1 (HH + HH)
#define LDW0 (K0 + 4)
#define LDW1 (K1 + 4)
#define SMEMB ((64 * LDW1 + 48) * 4)

// A operands stored TRANSPOSED [k][batch] as pre-split (hi,lo) float2
__device__ float2 g_x2[(size_t)TT * II * BB];
__device__ float2 g_h0[2][HH * BB];
__device__ float2 g_h1[2][HH * BB];
__device__ unsigned g_cnt;
__device__ unsigned g_gen;

__device__ __forceinline__ void gbar() {
    __syncthreads();
    if (threadIdx.x == 0) {
        unsigned old = *((volatile unsigned*)&g_gen);
        __threadfence();
        if (atomicAdd(&g_cnt, 1u) == NCTA - 1) {
            atomicExch(&g_cnt, 0u);
            __threadfence();
            atomicAdd(&g_gen, 1u);
        } else {
            while (*((volatile unsigned*)&g_gen) == old) { }
        }
        __threadfence();
    }
    __syncthreads();
}

__device__ __forceinline__ void split(float x, unsigned& hi, unsigned& lo) {
    asm("cvt.rna.tf32.f32 %0, %1;" : "=r"(hi) : "f"(x));
    float r = x - __uint_as_float(hi);
    asm("cvt.rna.tf32.f32 %0, %1;" : "=r"(lo) : "f"(r));
}

__device__ __forceinline__ float2 split2(float x) {
    unsigned hi, lo;
    split(x, hi, lo);
    return make_float2(__uint_as_float(hi), __uint_as_float(lo));
}

__device__ __forceinline__ void mma8(float (&c)[4], float a0, float a1,
                                     float a2, float a3, float b0, float b1) {
    asm volatile(
        "mma.sync.aligned.m16n8k8.row.col.f32.tf32.tf32.f32 "
        "{%0,%1,%2,%3},{%4,%5,%6,%7},{%8,%9},{%0,%1,%2,%3};"
        : "+f"(c[0]), "+f"(c[1]), "+f"(c[2]), "+f"(c[3])
        : "r"(__float_as_uint(a0)), "r"(__float_as_uint(a1)),
          "r"(__float_as_uint(a2)), "r"(__float_as_uint(a3)),
          "r"(__float_as_uint(b0)), "r"(__float_as_uint(b1)));
}

__device__ __forceinline__ float sigm(float x) { return 1.0f / (1.0f + __expf(-x)); }
__device__ __forceinline__ float tanhx(float x) { return 1.0f - 2.0f / (__expf(2.0f * x) + 1.0f); }

// A: k-major [nk][BB] float2 (hi,lo), starting at local k=0. koff = global k
// offset for the weight index. Weights hi/lo in SMEM, pair-interleaved so
// (b[k+kk], b[k+kk+4]) is one float2.
__device__ __forceinline__ void gemm_span(float (&acc)[4][4],
                                          const float2* __restrict__ A, int nk, int koff,
                                          const float* __restrict__ WHi,
                                          const float* __restrict__ WLo,
                                          int ldw, int r0, int lane) {
    const int kk = lane & 3;
    const int gq = lane >> 2;
    const float2* p = A + kk * BB + r0;
#pragma unroll 4
    for (int k = 0; k < nk; k += 8) {
        float2 e0 = __ldcg(p + k * BB);
        float2 e1 = __ldcg(p + k * BB + 8);
        float2 e2 = __ldcg(p + (k + 4) * BB);
        float2 e3 = __ldcg(p + (k + 4) * BB + 8);
#pragma unroll
        for (int g = 0; g < 4; ++g) {
            int off = (g * 8 + gq) * ldw + (k + koff) + 2 * kk;
            float2 bh = *reinterpret_cast<const float2*>(WHi + off);
            float2 bl = *reinterpret_cast<const float2*>(WLo + off);
            mma8(acc[g], e0.x, e1.x, e2.x, e3.x, bh.x, bh.y);
            mma8(acc[g], e0.y, e1.y, e2.y, e3.y, bh.x, bh.y);
            mma8(acc[g], e0.x, e1.x, e2.x, e3.x, bl.x, bl.y);
        }
    }
}

__global__ void __launch_bounds__(NTH, 1)
lstm_kernel(const float* __restrict__ x, const float* __restrict__ h0in,
            const float* __restrict__ c0in,
            const float* __restrict__ Wih0, const float* __restrict__ Whh0,
            const float* __restrict__ bih0, const float* __restrict__ bhh0,
            const float* __restrict__ Wih1, const float* __restrict__ Whh1,
            const float* __restrict__ bih1, const float* __restrict__ bhh1,
            const float* __restrict__ Wlin, const float* __restrict__ blin,
            float* __restrict__ out) {
    extern __shared__ float sh[];
    const int tid = threadIdx.x;
    const int cta = blockIdx.x;
    const int layer = cta >> 6;
    const int sub = cta & 63;
    const int cb = (sub >> 1) * 8;     // first hidden column (8 per CTA)
    const int bhalf = sub & 1;
    const int K = layer ? K1 : K0;
    const int ldw = layer ? LDW1 : LDW0;
    const int KX = layer ? HH : II;
    const float* Wih = layer ? Wih1 : Wih0;
    const float* Whh = layer ? Whh1 : Whh0;
    const float* bi = layer ? bih1 : bih0;
    const float* bh = layer ? bhh1 : bhh0;

    float* WHi = sh;
    float* WLo = sh + 32 * ldw;
    float* bs = sh + 64 * ldw;
    float* wl = bs + 32;

    // init: transpose+split x and h0 into k-major scratch; out = b_lin
    {
        int g = cta * NTH + tid, gs = NCTA * NTH;
        for (size_t i = g; i < (size_t)TT * BB * II; i += gs) {
            size_t t = i / (BB * II);
            int rem = (int)(i - t * (BB * II));
            int r = rem / II, k = rem - r * II;
            g_x2[t * (II * BB) + k * BB + r] = split2(x[i]);
        }
        for (int i = g; i < BB * HH; i += gs) {
            int r = i / HH, k = i - r * HH;
            g_h0[1][k * BB + r] = split2(h0in[i]);
            g_h1[1][k * BB + r] = split2(h0in[BB * HH + i]);
        }
        float bl = blin[0];
        for (int i = g; i < TT * BB; i += gs) out[i] = bl;
    }

    // stage split weights (pair-interleaved within each 8-wide k-group)
    for (int i = tid; i < 32 * K; i += NTH) {
        int n = i / K, k = i - n * K;
        int row = (n >> 3) * HH + cb + (n & 7);
        float wv = (k < KX) ? Wih[row * KX + k] : Whh[row * HH + (k - KX)];
        unsigned hi, lo;
        split(wv, hi, lo);
        int ko = n * ldw + (k & ~7) + 2 * (k & 3) + ((k >> 2) & 1);
        WHi[ko] = __uint_as_float(hi);
        WLo[ko] = __uint_as_float(lo);
    }
    if (tid < 32) {
        int row = (tid >> 3) * HH + cb + (tid & 7);
        bs[tid] = bi[row] + bh[row];
    }
    if (tid < 8) wl[tid] = layer ? Wlin[cb + tid] : 0.0f;
    __syncthreads();

    const int w = tid >> 5;
    const int lane = tid & 31;
    const int r0 = 64 * bhalf + 16 * w + (lane >> 2);  // batch rows r0, r0+8
    const int j0 = 2 * (lane & 3);
    const float* c0p = c0in + layer * BB * HH;
    float cs[4];
    cs[0] = c0p[r0 * HH + cb + j0];
    cs[1] = c0p[r0 * HH + cb + j0 + 1];
    cs[2] = c0p[(r0 + 8) * HH + cb + j0];
    cs[3] = c0p[(r0 + 8) * HH + cb + j0 + 1];

    float bz0[4], bz1[4];
#pragma unroll
    for (int g = 0; g < 4; ++g) {
        bz0[g] = bs[g * 8 + j0];
        bz1[g] = bs[g * 8 + j0 + 1];
    }
    const float wl0 = wl[j0], wl1 = wl[j0 + 1];

    gbar();

#pragma unroll 1
    for (int s = 0; s <= TT; ++s) {
        if (layer == 0) {
            if (s < TT) {
                float acc[4][4];
#pragma unroll
                for (int g = 0; g < 4; ++g) {
                    acc[g][0] = bz0[g]; acc[g][1] = bz1[g];
                    acc[g][2] = bz0[g]; acc[g][3] = bz1[g];
                }
                gemm_span(acc, g_x2 + (size_t)s * (II * BB), II, 0, WHi, WLo, ldw, r0, lane);
                gemm_span(acc, g_h0[(s + 1) & 1], HH, II, WHi, WLo, ldw, r0, lane);
                float2* hb2 = g_h0[s & 1];
#pragma unroll
                for (int e = 0; e < 4; ++e) {
                    float ig = sigm(acc[0][e]);
                    float fg = sigm(acc[1][e]);
                    float gg = tanhx(acc[2][e]);
                    float og = sigm(acc[3][e]);
                    float c = fg * cs[e] + ig * gg;
                    cs[e] = c;
                    float hv = og * tanhx(c);
                    int rr = (e & 2) ? (r0 + 8) : r0;
                    hb2[(cb + j0 + (e & 1)) * BB + rr] = split2(hv);
                }
            }
        } else {
            if (s >= 1) {
                int t = s - 1;
                float acc[4][4];
#pragma unroll
                for (int g = 0; g < 4; ++g) {
                    acc[g][0] = bz0[g]; acc[g][1] = bz1[g];
                    acc[g][2] = bz0[g]; acc[g][3] = bz1[g];
                }
                gemm_span(acc, g_h0[t & 1], HH, 0, WHi, WLo, ldw, r0, lane);
                gemm_span(acc, g_h1[s & 1], HH, HH, WHi, WLo, ldw, r0, lane);
                float2* hb2 = g_h1[t & 1];
                float h[4];
#pragma unroll
                for (int e = 0; e < 4; ++e) {
                    float ig = sigm(acc[0][e]);
                    float fg = sigm(acc[1][e]);
                    float gg = tanhx(acc[2][e]);
                    float og = sigm(acc[3][e]);
                    float c = fg * cs[e] + ig * gg;
                    cs[e] = c;
                    h[e] = og * tanhx(c);
                    int rr = (e & 2) ? (r0 + 8) : r0;
                    hb2[(cb + j0 + (e & 1)) * BB + rr] = split2(h[e]);
                }
                float p0 = h[0] * wl0 + h[1] * wl1;
                float p1 = h[2] * wl0 + h[3] * wl1;
                p0 += __shfl_xor_sync(0xffffffffu, p0, 1);
                p0 += __shfl_xor_sync(0xffffffffu, p0, 2);
                p1 += __shfl_xor_sync(0xffffffffu, p1, 1);
                p1 += __shfl_xor_sync(0xffffffffu, p1, 2);
                if ((lane & 3) == 0) {
                    atomicAdd(out + (size_t)t * BB + r0, p0);
                    atomicAdd(out + (size_t)t * BB + r0 + 8, p1);
                }
            }
        }
        gbar();
    }
}

extern "C" void kernel_launch(void* const* d_in, const int* in_sizes, int n_in,
                              void* d_out, int out_size) {
    (void)in_sizes; (void)n_in; (void)out_size;
    cudaFuncSetAttribute(lstm_kernel, cudaFuncAttributeMaxDynamicSharedMemorySize, SMEMB);
    lstm_kernel<<<NCTA, NTH, SMEMB>>>(
        (const float*)d_in[0], (const float*)d_in[1], (const float*)d_in[2],
        (const float*)d_in[3], (const float*)d_in[4], (const float*)d_in[5],
        (const float*)d_in[6], (const float*)d_in[7], (const float*)d_in[8],
        (const float*)d_in[9], (const float*)d_in[10], (const float*)d_in[11],
        (const float*)d_in[12], (float*)d_out);
}

// round 10
// speedup vs baseline: 1.6354x; 1.2693x over previous
#include <cuda_runtime.h>
#include <cstdint>

#define TT 2048
#define BB 128
#define HH 256
#define II 64
#define NCTA 128
#define NTH 256
#define K0 (II + HH)
#define K1 (HH + HH)
#define LDW0 (K0 + 4)
#define LDW1 (K1 + 4)
#define RED_OFF (64 * LDW1 + 64)
#define SMEMB ((RED_OFF + 2048) * 4)

// A operands stored TRANSPOSED [k][batch] as pre-split (hi,lo) float2
__device__ float2 g_x2[(size_t)TT * II * BB];
__device__ float2 g_h0[2][HH * BB];
__device__ float2 g_h1[2][HH * BB];
__device__ unsigned g_cnt;
__device__ unsigned g_gen;

__device__ __forceinline__ void gbar() {
    __syncthreads();
    if (threadIdx.x == 0) {
        unsigned old = *((volatile unsigned*)&g_gen);
        __threadfence();
        if (atomicAdd(&g_cnt, 1u) == NCTA - 1) {
            atomicExch(&g_cnt, 0u);
            __threadfence();
            atomicAdd(&g_gen, 1u);
        } else {
            while (*((volatile unsigned*)&g_gen) == old) { }
        }
        __threadfence();
    }
    __syncthreads();
}

__device__ __forceinline__ void split(float x, unsigned& hi, unsigned& lo) {
    asm("cvt.rna.tf32.f32 %0, %1;" : "=r"(hi) : "f"(x));
    float r = x - __uint_as_float(hi);
    asm("cvt.rna.tf32.f32 %0, %1;" : "=r"(lo) : "f"(r));
}

__device__ __forceinline__ float2 split2(float x) {
    unsigned hi, lo;
    split(x, hi, lo);
    return make_float2(__uint_as_float(hi), __uint_as_float(lo));
}

__device__ __forceinline__ void mma8(float (&c)[4], float a0, float a1,
                                     float a2, float a3, float b0, float b1) {
    asm volatile(
        "mma.sync.aligned.m16n8k8.row.col.f32.tf32.tf32.f32 "
        "{%0,%1,%2,%3},{%4,%5,%6,%7},{%8,%9},{%0,%1,%2,%3};"
        : "+f"(c[0]), "+f"(c[1]), "+f"(c[2]), "+f"(c[3])
        : "r"(__float_as_uint(a0)), "r"(__float_as_uint(a1)),
          "r"(__float_as_uint(a2)), "r"(__float_as_uint(a3)),
          "r"(__float_as_uint(b0)), "r"(__float_as_uint(b1)));
}

__device__ __forceinline__ float sigm(float x) { return 1.0f / (1.0f + __expf(-x)); }
__device__ __forceinline__ float tanhx(float x) { return 1.0f - 2.0f / (__expf(2.0f * x) + 1.0f); }

// A: k-major [nk][BB] float2 (hi,lo). koff = global k offset into weights.
// mma terms interleaved across gates so same-acc mmas are 4 issues apart.
__device__ __forceinline__ void gemm_span(float (&acc)[4][4],
                                          const float2* __restrict__ A, int nk, int koff,
                                          const float* __restrict__ WHi,
                                          const float* __restrict__ WLo,
                                          int ldw, int r0, int lane) {
    const int kk = lane & 3;
    const int gq = lane >> 2;
    const float2* p = A + kk * BB + r0;
    const float* wh = WHi + gq * ldw + koff + 2 * kk;
    const float* wo = WLo + gq * ldw + koff + 2 * kk;
#pragma unroll 4
    for (int k = 0; k < nk; k += 8) {
        float2 e0 = __ldcg(p + k * BB);
        float2 e1 = __ldcg(p + k * BB + 8);
        float2 e2 = __ldcg(p + (k + 4) * BB);
        float2 e3 = __ldcg(p + (k + 4) * BB + 8);
        float2 bh[4], bl[4];
#pragma unroll
        for (int g = 0; g < 4; ++g) {
            bh[g] = *reinterpret_cast<const float2*>(wh + g * 8 * ldw + k);
            bl[g] = *reinterpret_cast<const float2*>(wo + g * 8 * ldw + k);
        }
#pragma unroll
        for (int g = 0; g < 4; ++g)
            mma8(acc[g], e0.x, e1.x, e2.x, e3.x, bh[g].x, bh[g].y);
#pragma unroll
        for (int g = 0; g < 4; ++g)
            mma8(acc[g], e0.y, e1.y, e2.y, e3.y, bh[g].x, bh[g].y);
#pragma unroll
        for (int g = 0; g < 4; ++g)
            mma8(acc[g], e0.x, e1.x, e2.x, e3.x, bl[g].x, bl[g].y);
    }
}

__global__ void __launch_bounds__(NTH, 1)
lstm_kernel(const float* __restrict__ x, const float* __restrict__ h0in,
            const float* __restrict__ c0in,
            const float* __restrict__ Wih0, const float* __restrict__ Whh0,
            const float* __restrict__ bih0, const float* __restrict__ bhh0,
            const float* __restrict__ Wih1, const float* __restrict__ Whh1,
            const float* __restrict__ bih1, const float* __restrict__ bhh1,
            const float* __restrict__ Wlin, const float* __restrict__ blin,
            float* __restrict__ out) {
    extern __shared__ float sh[];
    const int tid = threadIdx.x;
    const int cta = blockIdx.x;
    const int layer = cta >> 6;
    const int sub = cta & 63;
    const int cb = (sub >> 1) * 8;     // first hidden column (8 per CTA)
    const int bhalf = sub & 1;
    const int K = layer ? K1 : K0;
    const int ldw = layer ? LDW1 : LDW0;
    const int KX = layer ? HH : II;
    const float* Wih = layer ? Wih1 : Wih0;
    const float* Whh = layer ? Whh1 : Whh0;
    const float* bi = layer ? bih1 : bih0;
    const float* bh = layer ? bhh1 : bhh0;

    float* WHi = sh;
    float* WLo = sh + 32 * ldw;
    float* bs = sh + 64 * ldw;
    float* wl = bs + 32;
    float4* red = (float4*)(sh + RED_OFF);

    // init: transpose+split x and h0 into k-major scratch; out = b_lin
    {
        int g = cta * NTH + tid, gs = NCTA * NTH;
        for (size_t i = g; i < (size_t)TT * BB * II; i += gs) {
            size_t t = i / (BB * II);
            int rem = (int)(i - t * (BB * II));
            int r = rem / II, k = rem - r * II;
            g_x2[t * (II * BB) + k * BB + r] = split2(x[i]);
        }
        for (int i = g; i < BB * HH; i += gs) {
            int r = i / HH, k = i - r * HH;
            g_h0[1][k * BB + r] = split2(h0in[i]);
            g_h1[1][k * BB + r] = split2(h0in[BB * HH + i]);
        }
        float bl = blin[0];
        for (int i = g; i < TT * BB; i += gs) out[i] = bl;
    }

    // stage split weights (pair-interleaved within each 8-wide k-group)
    for (int i = tid; i < 32 * K; i += NTH) {
        int n = i / K, k = i - n * K;
        int row = (n >> 3) * HH + cb + (n & 7);
        float wv = (k < KX) ? Wih[row * KX + k] : Whh[row * HH + (k - KX)];
        unsigned hi, lo;
        split(wv, hi, lo);
        int ko = n * ldw + (k & ~7) + 2 * (k & 3) + ((k >> 2) & 1);
        WHi[ko] = __uint_as_float(hi);
        WLo[ko] = __uint_as_float(lo);
    }
    if (tid < 32) {
        int row = (tid >> 3) * HH + cb + (tid & 7);
        bs[tid] = bi[row] + bh[row];
    }
    if (tid < 8) wl[tid] = layer ? Wlin[cb + tid] : 0.0f;
    __syncthreads();

    const int w = tid >> 5;            // 8 warps
    const int wk = w & 1;              // K-half
    const int wr = w >> 1;             // row tile 0..3
    const int lane = tid & 31;
    const int r0 = 64 * bhalf + 16 * wr + (lane >> 2);  // rows r0, r0+8
    const int j0 = 2 * (lane & 3);

    float cs[4] = {0.f, 0.f, 0.f, 0.f};
    if (wk == 0) {
        const float* c0p = c0in + layer * BB * HH;
        cs[0] = c0p[r0 * HH + cb + j0];
        cs[1] = c0p[r0 * HH + cb + j0 + 1];
        cs[2] = c0p[(r0 + 8) * HH + cb + j0];
        cs[3] = c0p[(r0 + 8) * HH + cb + j0 + 1];
    }

    float bz0[4], bz1[4];
#pragma unroll
    for (int g = 0; g < 4; ++g) {
        bz0[g] = bs[g * 8 + j0];
        bz1[g] = bs[g * 8 + j0 + 1];
    }
    const float wl0 = wl[j0], wl1 = wl[j0 + 1];

    gbar();

#pragma unroll 1
    for (int s = 0; s <= TT; ++s) {
        const bool active = layer ? (s >= 1) : (s < TT);
        float acc[4][4];
        if (active) {
            if (wk == 0) {
#pragma unroll
                for (int g = 0; g < 4; ++g) {
                    acc[g][0] = bz0[g]; acc[g][1] = bz1[g];
                    acc[g][2] = bz0[g]; acc[g][3] = bz1[g];
                }
            } else {
#pragma unroll
                for (int g = 0; g < 4; ++g)
                    acc[g][0] = acc[g][1] = acc[g][2] = acc[g][3] = 0.0f;
            }
            if (layer == 0) {
                const float2* hprev = g_h0[(s + 1) & 1];
                if (wk == 0) {
                    gemm_span(acc, g_x2 + (size_t)s * (II * BB), II, 0, WHi, WLo, ldw, r0, lane);
                    gemm_span(acc, hprev, 96, II, WHi, WLo, ldw, r0, lane);
                } else {
                    gemm_span(acc, hprev + 96 * BB, 160, 160, WHi, WLo, ldw, r0, lane);
                }
            } else {
                int t = s - 1;
                if (wk == 0) {
                    gemm_span(acc, g_h0[t & 1], HH, 0, WHi, WLo, ldw, r0, lane);
                } else {
                    gemm_span(acc, g_h1[s & 1], HH, HH, WHi, WLo, ldw, r0, lane);
                }
            }
            if (wk == 1) {
#pragma unroll
                for (int g = 0; g < 4; ++g)
                    red[g * 128 + wr * 32 + lane] =
                        make_float4(acc[g][0], acc[g][1], acc[g][2], acc[g][3]);
            }
        }
        __syncthreads();
        if (active && wk == 0) {
#pragma unroll
            for (int g = 0; g < 4; ++g) {
                float4 v = red[g * 128 + wr * 32 + lane];
                acc[g][0] += v.x; acc[g][1] += v.y;
                acc[g][2] += v.z; acc[g][3] += v.w;
            }
            float h[4];
#pragma unroll
            for (int e = 0; e < 4; ++e) {
                float ig = sigm(acc[0][e]);
                float fg = sigm(acc[1][e]);
                float gg = tanhx(acc[2][e]);
                float og = sigm(acc[3][e]);
                float c = fg * cs[e] + ig * gg;
                cs[e] = c;
                h[e] = og * tanhx(c);
            }
            float2* hb2 = layer ? g_h1[(s - 1) & 1] : g_h0[s & 1];
#pragma unroll
            for (int e = 0; e < 4; ++e) {
                int rr = (e & 2) ? (r0 + 8) : r0;
                hb2[(cb + j0 + (e & 1)) * BB + rr] = split2(h[e]);
            }
            if (layer == 1) {
                int t = s - 1;
                float p0 = h[0] * wl0 + h[1] * wl1;
                float p1 = h[2] * wl0 + h[3] * wl1;
                p0 += __shfl_xor_sync(0xffffffffu, p0, 1);
                p0 += __shfl_xor_sync(0xffffffffu, p0, 2);
                p1 += __shfl_xor_sync(0xffffffffu, p1, 1);
                p1 += __shfl_xor_sync(0xffffffffu, p1, 2);
                if ((lane & 3) == 0) {
                    atomicAdd(out + (size_t)t * BB + r0, p0);
                    atomicAdd(out + (size_t)t * BB + r0 + 8, p1);
                }
            }
        }
        gbar();
    }
}

extern "C" void kernel_launch(void* const* d_in, const int* in_sizes, int n_in,
                              void* d_out, int out_size) {
    (void)in_sizes; (void)n_in; (void)out_size;
    cudaFuncSetAttribute(lstm_kernel, cudaFuncAttributeMaxDynamicSharedMemorySize, SMEMB);
    lstm_kernel<<<NCTA, NTH, SMEMB>>>(
        (const float*)d_in[0], (const float*)d_in[1], (const float*)d_in[2],
        (const float*)d_in[3], (const float*)d_in[4], (const float*)d_in[5],
        (const float*)d_in[6], (const float*)d_in[7], (const float*)d_in[8],
        (const float*)d_in[9], (const float*)d_in[10], (const float*)d_in[11],
        (const float*)d_in[12], (float*)d_out);
}